// round 14
// baseline (speedup 1.0000x reference)
#include <cuda_runtime.h>
#include <cuda_fp16.h>
#include <cstdint>
#include <math.h>

// ---------------- problem constants ----------------
#define KBATCH 8
#define KSEQ   2048
#define KDIM   512
#define KROWS  (KBATCH*KSEQ)   // 16384

// ---------------- scratch (device globals; no allocations) ----------------
__device__ __half  g_in  [3][(size_t)KROWS * KDIM];  // Q,K,V inputs fp16
__device__ __half  g_w   [3][(size_t)KDIM * KDIM];   // W^T fp16 [e][d] = [N,K]
__device__ __half  g_qkv [3][(size_t)KROWS * KDIM];  // q_s, k_s, v_s fp16
__device__ __half  g_vt  [(size_t)KBATCH * KDIM * KSEQ]; // v_s^T fp16 [B][D][S]
__device__ float   g_s   [(size_t)KBATCH * KSEQ * KSEQ]; // scores f32
__device__ __half  g_ph  [(size_t)KBATCH * KSEQ * KSEQ]; // probs fp16

// ---------------- helpers ----------------
__device__ __forceinline__ uint32_t smem_u32(const void* p) {
    uint32_t a;
    asm("{ .reg .u64 t; cvta.to.shared.u64 t, %1; cvt.u32.u64 %0, t; }" : "=r"(a) : "l"(p));
    return a;
}
__device__ __forceinline__ uint32_t pack2h(__half a, __half b) {
    return (uint32_t)__half_as_ushort(a) | ((uint32_t)__half_as_ushort(b) << 16);
}
__device__ __forceinline__ void ldmx4(uint32_t& r0, uint32_t& r1, uint32_t& r2, uint32_t& r3,
                                      uint32_t addr) {
    asm volatile("ldmatrix.sync.aligned.m8n8.x4.shared.b16 {%0,%1,%2,%3}, [%4];"
                 : "=r"(r0), "=r"(r1), "=r"(r2), "=r"(r3) : "r"(addr));
}
__device__ __forceinline__ void mma_f16(float* c, const uint32_t* a, uint32_t b0, uint32_t b1) {
    asm volatile("mma.sync.aligned.m16n8k16.row.col.f32.f16.f16.f32 "
                 "{%0,%1,%2,%3}, {%4,%5,%6,%7}, {%8,%9}, {%0,%1,%2,%3};"
                 : "+f"(c[0]), "+f"(c[1]), "+f"(c[2]), "+f"(c[3])
                 : "r"(a[0]), "r"(a[1]), "r"(a[2]), "r"(a[3]), "r"(b0), "r"(b1));
}
#define CP16(dst, src) \
    asm volatile("cp.async.cg.shared.global [%0], [%1], 16;" :: "r"(dst), "l"(src))
#define CP_COMMIT() asm volatile("cp.async.commit_group;" ::: "memory")

__device__ __forceinline__ float ssc() { return 0.044194173824159216f; } // 1/sqrt(512)

// ---------------- HMMA GEMM: 256 threads, CTA 128x128, warp tile 64x32 ----------------
// 2 CTAs per SM, 16 warps/SM. Single-term fp16 (AhBh).
// EPI 1: *scale + mask -> f32    EPI 2: plain -> f32
// EPI 4: +bias(select by z from aux/aux2/aux3) -> single fp16 (Ch)
#define TILE_M 128
#define TILE_N 128
#define TILE_K 32
#define GT 256
#define NST 4
#define PSTR 40                     // padded smem row stride (halves) -> 80 B/row
#define T_B (128 * PSTR * 2)        // 10240 bytes per 128x32 fp16 tile
#define STB (2 * T_B)               // stage: Ah + Bh
#define SMEM_T (NST * STB)          // 81920

template<int EPI>
__global__ __launch_bounds__(GT, 2)
void gemm_hmma(const __half* __restrict__ Ah,
               const __half* __restrict__ Bh,
               const float* __restrict__ aux,
               const float* __restrict__ aux2,
               const float* __restrict__ aux3,
               float* __restrict__ C,
               __half* __restrict__ Ch,
               int N, int K,
               size_t sA, size_t sB, size_t sC, size_t sAux)
{
    extern __shared__ char sm[];
    const uint32_t sb = smem_u32(sm);

    Ah  += sA   * (size_t)blockIdx.z;
    Bh  += sB   * (size_t)blockIdx.z;
    C   += sC   * (size_t)blockIdx.z;
    Ch  += sC   * (size_t)blockIdx.z;
    aux += sAux * (size_t)blockIdx.z;
    const float* bias = aux;
    if (EPI == 4) bias = (blockIdx.z == 0) ? aux : (blockIdx.z == 1) ? aux2 : aux3;

    const int t    = threadIdx.x;
    const int lane = t & 31;
    const int w    = t >> 5;        // 0..7
    const int wm   = w & 1;         // warp row (2) -> M offset 64*wm
    const int wn   = w >> 1;        // warp col (4) -> N offset 32*wn
    const int bm   = blockIdx.y * TILE_M;
    const int bn   = blockIdx.x * TILE_N;

    const int cr = t >> 2;          // 0..63
    const int cc = t & 3;           // 16B chunk within 64B row

    const int a_r  = wm * 64 + (lane & 15);
    const int a_c8 = (lane >> 4) * 8;
    const int b_r  = wn * 32 + (lane & 7) + ((lane >> 4) & 1) * 8;
    const int b_c8 = ((lane >> 3) & 1) * 8;

    float acc[4][4][4];             // 4 m16-tiles x 4 n8-tiles
    #pragma unroll
    for (int i = 0; i < 4; ++i)
        #pragma unroll
        for (int j = 0; j < 4; ++j)
            #pragma unroll
            for (int e = 0; e < 4; ++e) acc[i][j][e] = 0.0f;

    const int nch = K / TILE_K;

    auto issue = [&](int j, int s) {
        const size_t kco = (size_t)j * TILE_K + cc * 8;
        const uint32_t base = sb + (uint32_t)(s * STB);
        #pragma unroll
        for (int p = 0; p < 2; ++p) {
            const int row = cr + p * 64;
            const uint32_t doff = (uint32_t)(row * (PSTR * 2) + cc * 16);
            CP16(base + doff,       Ah + (size_t)(bm + row) * K + kco);
            CP16(base + T_B + doff, Bh + (size_t)(bn + row) * K + kco);
        }
    };

    // prologue
    #pragma unroll
    for (int j = 0; j < NST - 1; ++j) {
        if (j < nch) issue(j, j);
        CP_COMMIT();
    }

    for (int i = 0; i < nch; ++i) {
        asm volatile("cp.async.wait_group %0;" :: "n"(NST - 2) : "memory");
        __syncthreads();

        const int jn = i + NST - 1;
        if (jn < nch) issue(jn, jn % NST);
        CP_COMMIT();

        const int s = i % NST;
        const uint32_t sAH = sb + (uint32_t)(s * STB);
        const uint32_t sBH = sAH + T_B;

        #pragma unroll
        for (int h = 0; h < 2; ++h) {
            const uint32_t bcol = (uint32_t)((h * 16 + b_c8) * 2);
            uint32_t bh[2][4];
            #pragma unroll
            for (int np = 0; np < 2; ++np) {
                const uint32_t boff = (uint32_t)((b_r + np * 16) * (PSTR * 2)) + bcol;
                ldmx4(bh[np][0], bh[np][1], bh[np][2], bh[np][3], sBH + boff);
            }
            const uint32_t acol = (uint32_t)((h * 16 + a_c8) * 2);
            #pragma unroll
            for (int mp = 0; mp < 2; ++mp) {
                uint32_t ahr[2][4];
                #pragma unroll
                for (int m2 = 0; m2 < 2; ++m2) {
                    const uint32_t aoff =
                        (uint32_t)((a_r + (mp * 2 + m2) * 16) * (PSTR * 2)) + acol;
                    ldmx4(ahr[m2][0], ahr[m2][1], ahr[m2][2], ahr[m2][3], sAH + aoff);
                }
                #pragma unroll
                for (int np = 0; np < 2; ++np)
                    #pragma unroll
                    for (int m2 = 0; m2 < 2; ++m2) {
                        mma_f16(acc[mp*2+m2][2*np],   ahr[m2], bh[np][0], bh[np][1]);
                        mma_f16(acc[mp*2+m2][2*np+1], ahr[m2], bh[np][2], bh[np][3]);
                    }
            }
        }
    }

    // ---------------- epilogue ----------------
    const int er = (lane >> 2);
    const int ec = (lane & 3) * 2;
    #pragma unroll
    for (int mt = 0; mt < 4; ++mt) {
        #pragma unroll
        for (int nt = 0; nt < 4; ++nt) {
            const int col = bn + wn * 32 + nt * 8 + ec;
            #pragma unroll
            for (int half = 0; half < 2; ++half) {
                const int row = bm + wm * 64 + mt * 16 + er + half * 8;
                float x0 = acc[mt][nt][2*half + 0];
                float x1 = acc[mt][nt][2*half + 1];
                if (EPI == 4) {
                    x0 += bias[col];
                    x1 += bias[col + 1];
                }
                if (EPI == 1) {
                    const float2 m2 = *reinterpret_cast<const float2*>(&aux[(size_t)row * N + col]);
                    x0 = fmaf(x0, ssc(), m2.x);
                    x1 = fmaf(x1, ssc(), m2.y);
                }
                const size_t o = (size_t)row * N + col;
                if (EPI == 4) {
                    *reinterpret_cast<uint32_t*>(&Ch[o]) =
                        pack2h(__float2half(x0), __float2half(x1));
                } else {
                    *reinterpret_cast<float2*>(&C[o]) = make_float2(x0, x1);
                }
            }
        }
    }
}

// ---------------- fused input convert: 3 tensors -> single fp16 ----------------
__global__ __launch_bounds__(256)
void convert_inputs(const float* __restrict__ q, const float* __restrict__ k,
                    const float* __restrict__ v, __half* __restrict__ dh)
{
    const size_t ISZ = (size_t)KROWS * KDIM;
    const float* src = (blockIdx.z == 0) ? q : (blockIdx.z == 1) ? k : v;
    __half* oh = dh + blockIdx.z * ISZ;
    const size_t i = ((size_t)blockIdx.x * 256 + threadIdx.x) * 4;
    float4 x = *reinterpret_cast<const float4*>(src + i);
    *reinterpret_cast<uint2*>(oh + i) =
        make_uint2(pack2h(__float2half(x.x), __float2half(x.y)),
                   pack2h(__float2half(x.z), __float2half(x.w)));
}

// ---------------- fused weight transpose -> single fp16 [e][d] ----------------
__global__ __launch_bounds__(256)
void wtrans(const float* __restrict__ wq, const float* __restrict__ wk,
            const float* __restrict__ wv, __half* __restrict__ dh)
{
    __shared__ float tile[32][33];
    const size_t WSZ = (size_t)KDIM * KDIM;
    const float* src = (blockIdx.z == 0) ? wq : (blockIdx.z == 1) ? wk : wv;
    __half* oh = dh + blockIdx.z * WSZ;
    const int bx = blockIdx.x * 32;
    const int by = blockIdx.y * 32;
    const int tx = threadIdx.x & 31;
    const int ty = threadIdx.x >> 5;
    #pragma unroll
    for (int i = 0; i < 32; i += 8)
        tile[ty + i][tx] = src[(size_t)(by + ty + i) * KDIM + bx + tx];
    __syncthreads();
    #pragma unroll
    for (int i = 0; i < 32; i += 8)
        oh[(size_t)(bx + ty + i) * KDIM + by + tx] = __float2half(tile[tx][ty + i]);
}

// ---------------- v transpose: fp16 [B][S][D] -> fp16 [B][D][S] ----------------
__global__ __launch_bounds__(256)
void vtrans(const __half* __restrict__ src, __half* __restrict__ dst)
{
    __shared__ __half tile[32][34];   // 34: odd 4B-bank stride for halves
    src += (size_t)KSEQ * KDIM * blockIdx.z;
    dst += (size_t)KDIM * KSEQ * blockIdx.z;
    const int bx = blockIdx.x * 32;   // D
    const int by = blockIdx.y * 32;   // S
    const int tx = threadIdx.x & 31;
    const int ty = threadIdx.x >> 5;
    #pragma unroll
    for (int i = 0; i < 32; i += 8)
        tile[ty + i][tx] = src[(size_t)(by + ty + i) * KDIM + bx + tx];
    __syncthreads();
    #pragma unroll
    for (int i = 0; i < 32; i += 8)
        dst[(size_t)(bx + ty + i) * KSEQ + by + tx] = tile[tx][ty + i];
}

// ---------------- row softmax over 2048, emits single fp16 probs ----------------
__global__ __launch_bounds__(256)
void softmax_kernel(const float* __restrict__ S, __half* __restrict__ Ph)
{
    __shared__ float buf[KSEQ];
    __shared__ float red[8];
    const float* p = S + (size_t)blockIdx.x * KSEQ;
    const int t = threadIdx.x, lane = t & 31, wid = t >> 5;

    float mx = -3.4e38f;
    #pragma unroll
    for (int i = t; i < KSEQ; i += 256) { float v = p[i]; buf[i] = v; mx = fmaxf(mx, v); }
    #pragma unroll
    for (int o = 16; o > 0; o >>= 1) mx = fmaxf(mx, __shfl_xor_sync(0xffffffffu, mx, o));
    if (lane == 0) red[wid] = mx;
    __syncthreads();
    mx = fmaxf(fmaxf(fmaxf(red[0], red[1]), fmaxf(red[2], red[3])),
               fmaxf(fmaxf(red[4], red[5]), fmaxf(red[6], red[7])));
    __syncthreads();

    float sum = 0.0f;
    #pragma unroll
    for (int i = t; i < KSEQ; i += 256) { float e = __expf(buf[i] - mx); buf[i] = e; sum += e; }
    #pragma unroll
    for (int o = 16; o > 0; o >>= 1) sum += __shfl_xor_sync(0xffffffffu, sum, o);
    if (lane == 0) red[wid] = sum;
    __syncthreads();
    sum = ((red[0] + red[1]) + (red[2] + red[3])) + ((red[4] + red[5]) + (red[6] + red[7]));
    const float inv = 1.0f / sum;

    __half* ph = Ph + (size_t)blockIdx.x * KSEQ;
    #pragma unroll
    for (int j = t; j < KSEQ / 2; j += 256) {
        float e0 = buf[2*j]     * inv;
        float e1 = buf[2*j + 1] * inv;
        *reinterpret_cast<uint32_t*>(ph + 2*j) =
            pack2h(__float2half(e0), __float2half(e1));
    }
}

// ---------------- launch ----------------
extern "C" void kernel_launch(void* const* d_in, const int* in_sizes, int n_in,
                              void* d_out, int out_size)
{
    (void)in_sizes; (void)n_in; (void)out_size;
    const float* Qin  = (const float*)d_in[0];
    const float* Kin  = (const float*)d_in[1];
    const float* Vin  = (const float*)d_in[2];
    const float* mask = (const float*)d_in[3];
    const float* Wq   = (const float*)d_in[4];
    const float* bq   = (const float*)d_in[5];
    const float* Wk   = (const float*)d_in[6];
    const float* bk   = (const float*)d_in[7];
    const float* Wv   = (const float*)d_in[8];
    const float* bv   = (const float*)d_in[9];
    float* out = (float*)d_out;

    float *s;
    __half *in16, *w16, *qkv, *vt, *ph;
    cudaGetSymbolAddress((void**)&in16, g_in);
    cudaGetSymbolAddress((void**)&w16,  g_w);
    cudaGetSymbolAddress((void**)&qkv,  g_qkv);
    cudaGetSymbolAddress((void**)&vt,   g_vt);
    cudaGetSymbolAddress((void**)&s,    g_s);
    cudaGetSymbolAddress((void**)&ph,   g_ph);

    cudaFuncSetAttribute(gemm_hmma<4>, cudaFuncAttributeMaxDynamicSharedMemorySize, SMEM_T);
    cudaFuncSetAttribute(gemm_hmma<1>, cudaFuncAttributeMaxDynamicSharedMemorySize, SMEM_T);
    cudaFuncSetAttribute(gemm_hmma<2>, cudaFuncAttributeMaxDynamicSharedMemorySize, SMEM_T);

    const size_t ISZ = (size_t)KROWS * KDIM;
    const size_t WSZ = (size_t)KDIM * KDIM;
    dim3 tb(256);

    // 1-2) preprocessing: inputs + weights -> single fp16
    convert_inputs<<<dim3((int)(ISZ / 4 / 256), 1, 3), tb>>>(Qin, Kin, Vin, in16);
    wtrans<<<dim3(16, 16, 3), tb>>>(Wq, Wk, Wv, w16);

    // 3) fused Q/K/V projections: one launch, z selects {input, weight, bias, output}
    //    M=16384, N=512, K=512 each -> grid (4, 128, 3)
    dim3 gp(KDIM / TILE_N, KROWS / TILE_M, 3);
    gemm_hmma<4><<<gp, GT, SMEM_T>>>(in16, w16, bq, bk, bv,
                                     nullptr, qkv, KDIM, KDIM,
                                     ISZ, WSZ, ISZ, 0);

    // 4) scores = q_s k_s^T * scale + mask  (per batch 2048x2048, K=512)
    dim3 gs(KSEQ / TILE_N, KSEQ / TILE_M, KBATCH);
    gemm_hmma<1><<<gs, GT, SMEM_T>>>(qkv + 0*ISZ, qkv + 1*ISZ, mask, nullptr, nullptr,
                                     s, nullptr, KSEQ, KDIM,
                                     (size_t)KSEQ * KDIM, (size_t)KSEQ * KDIM,
                                     (size_t)KSEQ * KSEQ, (size_t)KSEQ * KSEQ);

    // 5) v_s -> v_s^T (fp16 -> fp16)
    vtrans<<<dim3(KDIM / 32, KSEQ / 32, KBATCH), tb>>>(qkv + 2*ISZ, vt);

    // 6) softmax -> single fp16 probs
    softmax_kernel<<<KROWS, 256>>>(s, ph);

    // 7) out = probs @ v_s  (per batch 2048x512, K=2048)
    dim3 ga(KDIM / TILE_N, KSEQ / TILE_M, KBATCH);
    gemm_hmma<2><<<ga, GT, SMEM_T>>>(ph, vt, nullptr, nullptr, nullptr,
                                     out, nullptr, KDIM, KSEQ,
                                     (size_t)KSEQ * KSEQ, (size_t)KDIM * KSEQ,
                                     (size_t)KSEQ * KDIM, 0);
}

// round 15
// speedup vs baseline: 1.0762x; 1.0762x over previous
#include <cuda_runtime.h>
#include <cuda_fp16.h>
#include <cstdint>
#include <math.h>

// ---------------- problem constants ----------------
#define KBATCH 8
#define KSEQ   2048
#define KDIM   512
#define KROWS  (KBATCH*KSEQ)   // 16384

// ---------------- scratch (device globals; no allocations) ----------------
__device__ __half  g_in  [3][(size_t)KROWS * KDIM];  // Q,K,V inputs fp16
__device__ __half  g_w   [3][(size_t)KDIM * KDIM];   // W^T fp16 [e][d] = [N,K]
__device__ __half  g_qkv [3][(size_t)KROWS * KDIM];  // q_s, k_s, v_s fp16
__device__ __half  g_vt  [(size_t)KBATCH * KDIM * KSEQ]; // v_s^T fp16 [B][D][S]
__device__ float   g_s   [(size_t)KBATCH * KSEQ * KSEQ]; // scores f32
__device__ __half  g_ph  [(size_t)KBATCH * KSEQ * KSEQ]; // probs fp16

// ---------------- helpers ----------------
__device__ __forceinline__ uint32_t smem_u32(const void* p) {
    uint32_t a;
    asm("{ .reg .u64 t; cvta.to.shared.u64 t, %1; cvt.u32.u64 %0, t; }" : "=r"(a) : "l"(p));
    return a;
}
__device__ __forceinline__ uint32_t pack2h(__half a, __half b) {
    return (uint32_t)__half_as_ushort(a) | ((uint32_t)__half_as_ushort(b) << 16);
}
__device__ __forceinline__ void ldmx4(uint32_t& r0, uint32_t& r1, uint32_t& r2, uint32_t& r3,
                                      uint32_t addr) {
    asm volatile("ldmatrix.sync.aligned.m8n8.x4.shared.b16 {%0,%1,%2,%3}, [%4];"
                 : "=r"(r0), "=r"(r1), "=r"(r2), "=r"(r3) : "r"(addr));
}
__device__ __forceinline__ void mma_f16(float* c, const uint32_t* a, uint32_t b0, uint32_t b1) {
    asm volatile("mma.sync.aligned.m16n8k16.row.col.f32.f16.f16.f32 "
                 "{%0,%1,%2,%3}, {%4,%5,%6,%7}, {%8,%9}, {%0,%1,%2,%3};"
                 : "+f"(c[0]), "+f"(c[1]), "+f"(c[2]), "+f"(c[3])
                 : "r"(a[0]), "r"(a[1]), "r"(a[2]), "r"(a[3]), "r"(b0), "r"(b1));
}
#define CP16(dst, src) \
    asm volatile("cp.async.cg.shared.global [%0], [%1], 16;" :: "r"(dst), "l"(src))
#define CP_COMMIT() asm volatile("cp.async.commit_group;" ::: "memory")

__device__ __forceinline__ float ssc() { return 0.044194173824159216f; } // 1/sqrt(512)

// ---------------- HMMA GEMM: 128 threads, CTA 128x128, warp tile 64x64 ----------------
// (R13 shape: measured best). 2 CTAs per SM. Single-term fp16 (AhBh).
// EPI 1: *scale + mask -> f32    EPI 2: plain -> f32
// EPI 4: +bias(select by z from aux/aux2/aux3) -> single fp16 (Ch)
#define TILE_M 128
#define TILE_N 128
#define TILE_K 32
#define GT 128
#define NST 4
#define PSTR 40                     // padded smem row stride (halves) -> 80 B/row
#define T_B (128 * PSTR * 2)        // 10240 bytes per 128x32 fp16 tile
#define STB (2 * T_B)               // stage: Ah + Bh
#define SMEM_T (NST * STB)          // 81920

template<int EPI>
__global__ __launch_bounds__(GT, 2)
void gemm_hmma(const __half* __restrict__ Ah,
               const __half* __restrict__ Bh,
               const float* __restrict__ aux,
               const float* __restrict__ aux2,
               const float* __restrict__ aux3,
               float* __restrict__ C,
               __half* __restrict__ Ch,
               int N, int K,
               size_t sA, size_t sB, size_t sC, size_t sAux)
{
    extern __shared__ char sm[];
    const uint32_t sb = smem_u32(sm);

    Ah  += sA   * (size_t)blockIdx.z;
    Bh  += sB   * (size_t)blockIdx.z;
    C   += sC   * (size_t)blockIdx.z;
    Ch  += sC   * (size_t)blockIdx.z;
    aux += sAux * (size_t)blockIdx.z;
    const float* bias = aux;
    if (EPI == 4) bias = (blockIdx.z == 0) ? aux : (blockIdx.z == 1) ? aux2 : aux3;

    const int t    = threadIdx.x;
    const int lane = t & 31;
    const int w    = t >> 5;        // 0..3
    const int wm   = w & 1;         // warp row (2) -> M offset 64*wm
    const int wn   = w >> 1;        // warp col (2) -> N offset 64*wn
    const int bm   = blockIdx.y * TILE_M;
    const int bn   = blockIdx.x * TILE_N;

    const int cr = t >> 2;          // 0..31
    const int cc = t & 3;           // 16B chunk within 64B row

    const int a_r  = wm * 64 + (lane & 15);
    const int a_c8 = (lane >> 4) * 8;
    const int b_r  = wn * 64 + (lane & 7) + ((lane >> 4) & 1) * 8;
    const int b_c8 = ((lane >> 3) & 1) * 8;

    float acc[4][8][4];             // 4 m16-tiles x 8 n8-tiles
    #pragma unroll
    for (int i = 0; i < 4; ++i)
        #pragma unroll
        for (int j = 0; j < 8; ++j)
            #pragma unroll
            for (int e = 0; e < 4; ++e) acc[i][j][e] = 0.0f;

    const int nch = K / TILE_K;

    auto issue = [&](int j, int s) {
        const size_t kco = (size_t)j * TILE_K + cc * 8;
        const uint32_t base = sb + (uint32_t)(s * STB);
        #pragma unroll
        for (int p = 0; p < 4; ++p) {
            const int row = cr + p * 32;
            const uint32_t doff = (uint32_t)(row * (PSTR * 2) + cc * 16);
            CP16(base + doff,       Ah + (size_t)(bm + row) * K + kco);
            CP16(base + T_B + doff, Bh + (size_t)(bn + row) * K + kco);
        }
    };

    // prologue
    #pragma unroll
    for (int j = 0; j < NST - 1; ++j) {
        if (j < nch) issue(j, j);
        CP_COMMIT();
    }

    for (int i = 0; i < nch; ++i) {
        asm volatile("cp.async.wait_group %0;" :: "n"(NST - 2) : "memory");
        __syncthreads();

        const int jn = i + NST - 1;
        if (jn < nch) issue(jn, jn % NST);
        CP_COMMIT();

        const int s = i % NST;
        const uint32_t sAH = sb + (uint32_t)(s * STB);
        const uint32_t sBH = sAH + T_B;

        #pragma unroll
        for (int h = 0; h < 2; ++h) {
            const uint32_t bcol = (uint32_t)((h * 16 + b_c8) * 2);
            uint32_t bh[4][4];
            #pragma unroll
            for (int np = 0; np < 4; ++np) {
                const uint32_t boff = (uint32_t)((b_r + np * 16) * (PSTR * 2)) + bcol;
                ldmx4(bh[np][0], bh[np][1], bh[np][2], bh[np][3], sBH + boff);
            }
            const uint32_t acol = (uint32_t)((h * 16 + a_c8) * 2);
            #pragma unroll
            for (int mp = 0; mp < 2; ++mp) {
                uint32_t ahr[2][4];
                #pragma unroll
                for (int m2 = 0; m2 < 2; ++m2) {
                    const uint32_t aoff =
                        (uint32_t)((a_r + (mp * 2 + m2) * 16) * (PSTR * 2)) + acol;
                    ldmx4(ahr[m2][0], ahr[m2][1], ahr[m2][2], ahr[m2][3], sAH + aoff);
                }
                #pragma unroll
                for (int np = 0; np < 4; ++np)
                    #pragma unroll
                    for (int m2 = 0; m2 < 2; ++m2) {
                        mma_f16(acc[mp*2+m2][2*np],   ahr[m2], bh[np][0], bh[np][1]);
                        mma_f16(acc[mp*2+m2][2*np+1], ahr[m2], bh[np][2], bh[np][3]);
                    }
            }
        }
    }

    // ---------------- epilogue ----------------
    const int er = (lane >> 2);
    const int ec = (lane & 3) * 2;
    #pragma unroll
    for (int mt = 0; mt < 4; ++mt) {
        #pragma unroll
        for (int nt = 0; nt < 8; ++nt) {
            const int col = bn + wn * 64 + nt * 8 + ec;
            #pragma unroll
            for (int half = 0; half < 2; ++half) {
                const int row = bm + wm * 64 + mt * 16 + er + half * 8;
                float x0 = acc[mt][nt][2*half + 0];
                float x1 = acc[mt][nt][2*half + 1];
                if (EPI == 4) {
                    x0 += bias[col];
                    x1 += bias[col + 1];
                }
                if (EPI == 1) {
                    const float2 m2 = *reinterpret_cast<const float2*>(&aux[(size_t)row * N + col]);
                    x0 = fmaf(x0, ssc(), m2.x);
                    x1 = fmaf(x1, ssc(), m2.y);
                }
                const size_t o = (size_t)row * N + col;
                if (EPI == 4) {
                    *reinterpret_cast<uint32_t*>(&Ch[o]) =
                        pack2h(__float2half(x0), __float2half(x1));
                } else {
                    *reinterpret_cast<float2*>(&C[o]) = make_float2(x0, x1);
                }
            }
        }
    }
}

// ---------------- fused input convert: 3 tensors -> single fp16 ----------------
__global__ __launch_bounds__(256)
void convert_inputs(const float* __restrict__ q, const float* __restrict__ k,
                    const float* __restrict__ v, __half* __restrict__ dh)
{
    const size_t ISZ = (size_t)KROWS * KDIM;
    const float* src = (blockIdx.z == 0) ? q : (blockIdx.z == 1) ? k : v;
    __half* oh = dh + blockIdx.z * ISZ;
    const size_t i = ((size_t)blockIdx.x * 256 + threadIdx.x) * 4;
    float4 x = *reinterpret_cast<const float4*>(src + i);
    *reinterpret_cast<uint2*>(oh + i) =
        make_uint2(pack2h(__float2half(x.x), __float2half(x.y)),
                   pack2h(__float2half(x.z), __float2half(x.w)));
}

// ---------------- fused weight transpose -> single fp16 [e][d] ----------------
__global__ __launch_bounds__(256)
void wtrans(const float* __restrict__ wq, const float* __restrict__ wk,
            const float* __restrict__ wv, __half* __restrict__ dh)
{
    __shared__ float tile[32][33];
    const size_t WSZ = (size_t)KDIM * KDIM;
    const float* src = (blockIdx.z == 0) ? wq : (blockIdx.z == 1) ? wk : wv;
    __half* oh = dh + blockIdx.z * WSZ;
    const int bx = blockIdx.x * 32;
    const int by = blockIdx.y * 32;
    const int tx = threadIdx.x & 31;
    const int ty = threadIdx.x >> 5;
    #pragma unroll
    for (int i = 0; i < 32; i += 8)
        tile[ty + i][tx] = src[(size_t)(by + ty + i) * KDIM + bx + tx];
    __syncthreads();
    #pragma unroll
    for (int i = 0; i < 32; i += 8)
        oh[(size_t)(bx + ty + i) * KDIM + by + tx] = __float2half(tile[tx][ty + i]);
}

// ---------------- v transpose: fp16 [B][S][D] -> fp16 [B][D][S] ----------------
__global__ __launch_bounds__(256)
void vtrans(const __half* __restrict__ src, __half* __restrict__ dst)
{
    __shared__ __half tile[32][34];
    src += (size_t)KSEQ * KDIM * blockIdx.z;
    dst += (size_t)KDIM * KSEQ * blockIdx.z;
    const int bx = blockIdx.x * 32;   // D
    const int by = blockIdx.y * 32;   // S
    const int tx = threadIdx.x & 31;
    const int ty = threadIdx.x >> 5;
    #pragma unroll
    for (int i = 0; i < 32; i += 8)
        tile[ty + i][tx] = src[(size_t)(by + ty + i) * KDIM + bx + tx];
    __syncthreads();
    #pragma unroll
    for (int i = 0; i < 32; i += 8)
        dst[(size_t)(bx + ty + i) * KSEQ + by + tx] = tile[tx][ty + i];
}

// ---------------- row softmax over 2048, emits single fp16 probs ----------------
__global__ __launch_bounds__(256)
void softmax_kernel(const float* __restrict__ S, __half* __restrict__ Ph)
{
    __shared__ float buf[KSEQ];
    __shared__ float red[8];
    const float* p = S + (size_t)blockIdx.x * KSEQ;
    const int t = threadIdx.x, lane = t & 31, wid = t >> 5;

    float mx = -3.4e38f;
    #pragma unroll
    for (int i = t; i < KSEQ; i += 256) { float v = p[i]; buf[i] = v; mx = fmaxf(mx, v); }
    #pragma unroll
    for (int o = 16; o > 0; o >>= 1) mx = fmaxf(mx, __shfl_xor_sync(0xffffffffu, mx, o));
    if (lane == 0) red[wid] = mx;
    __syncthreads();
    mx = fmaxf(fmaxf(fmaxf(red[0], red[1]), fmaxf(red[2], red[3])),
               fmaxf(fmaxf(red[4], red[5]), fmaxf(red[6], red[7])));
    __syncthreads();

    float sum = 0.0f;
    #pragma unroll
    for (int i = t; i < KSEQ; i += 256) { float e = __expf(buf[i] - mx); buf[i] = e; sum += e; }
    #pragma unroll
    for (int o = 16; o > 0; o >>= 1) sum += __shfl_xor_sync(0xffffffffu, sum, o);
    if (lane == 0) red[wid] = sum;
    __syncthreads();
    sum = ((red[0] + red[1]) + (red[2] + red[3])) + ((red[4] + red[5]) + (red[6] + red[7]));
    const float inv = 1.0f / sum;

    __half* ph = Ph + (size_t)blockIdx.x * KSEQ;
    #pragma unroll
    for (int j = t; j < KSEQ / 2; j += 256) {
        float e0 = buf[2*j]     * inv;
        float e1 = buf[2*j + 1] * inv;
        *reinterpret_cast<uint32_t*>(ph + 2*j) =
            pack2h(__float2half(e0), __float2half(e1));
    }
}

// ---------------- launch ----------------
extern "C" void kernel_launch(void* const* d_in, const int* in_sizes, int n_in,
                              void* d_out, int out_size)
{
    (void)in_sizes; (void)n_in; (void)out_size;
    const float* Qin  = (const float*)d_in[0];
    const float* Kin  = (const float*)d_in[1];
    const float* Vin  = (const float*)d_in[2];
    const float* mask = (const float*)d_in[3];
    const float* Wq   = (const float*)d_in[4];
    const float* bq   = (const float*)d_in[5];
    const float* Wk   = (const float*)d_in[6];
    const float* bk   = (const float*)d_in[7];
    const float* Wv   = (const float*)d_in[8];
    const float* bv   = (const float*)d_in[9];
    float* out = (float*)d_out;

    float *s;
    __half *in16, *w16, *qkv, *vt, *ph;
    cudaGetSymbolAddress((void**)&in16, g_in);
    cudaGetSymbolAddress((void**)&w16,  g_w);
    cudaGetSymbolAddress((void**)&qkv,  g_qkv);
    cudaGetSymbolAddress((void**)&vt,   g_vt);
    cudaGetSymbolAddress((void**)&s,    g_s);
    cudaGetSymbolAddress((void**)&ph,   g_ph);

    cudaFuncSetAttribute(gemm_hmma<4>, cudaFuncAttributeMaxDynamicSharedMemorySize, SMEM_T);
    cudaFuncSetAttribute(gemm_hmma<1>, cudaFuncAttributeMaxDynamicSharedMemorySize, SMEM_T);
    cudaFuncSetAttribute(gemm_hmma<2>, cudaFuncAttributeMaxDynamicSharedMemorySize, SMEM_T);

    const size_t ISZ = (size_t)KROWS * KDIM;
    const size_t WSZ = (size_t)KDIM * KDIM;
    dim3 tb(256);

    // 1-2) preprocessing: inputs + weights -> single fp16
    convert_inputs<<<dim3((int)(ISZ / 4 / 256), 1, 3), tb>>>(Qin, Kin, Vin, in16);
    wtrans<<<dim3(16, 16, 3), tb>>>(Wq, Wk, Wv, w16);

    // 3) fused Q/K/V projections (one launch; z selects operands & bias)
    dim3 gp(KDIM / TILE_N, KROWS / TILE_M, 3);
    gemm_hmma<4><<<gp, GT, SMEM_T>>>(in16, w16, bq, bk, bv,
                                     nullptr, qkv, KDIM, KDIM,
                                     ISZ, WSZ, ISZ, 0);

    // 4) scores = q_s k_s^T * scale + mask  (per batch 2048x2048, K=512)
    dim3 gs(KSEQ / TILE_N, KSEQ / TILE_M, KBATCH);
    gemm_hmma<1><<<gs, GT, SMEM_T>>>(qkv + 0*ISZ, qkv + 1*ISZ, mask, nullptr, nullptr,
                                     s, nullptr, KSEQ, KDIM,
                                     (size_t)KSEQ * KDIM, (size_t)KSEQ * KDIM,
                                     (size_t)KSEQ * KSEQ, (size_t)KSEQ * KSEQ);

    // 5) v_s -> v_s^T (fp16 -> fp16)
    vtrans<<<dim3(KDIM / 32, KSEQ / 32, KBATCH), tb>>>(qkv + 2*ISZ, vt);

    // 6) softmax -> single fp16 probs
    softmax_kernel<<<KROWS, 256>>>(s, ph);

    // 7) out = probs @ v_s  (per batch 2048x512, K=2048)
    dim3 ga(KDIM / TILE_N, KSEQ / TILE_M, KBATCH);
    gemm_hmma<2><<<ga, GT, SMEM_T>>>(ph, vt, nullptr, nullptr, nullptr,
                                     out, nullptr, KDIM, KSEQ,
                                     (size_t)KSEQ * KSEQ, (size_t)KDIM * KSEQ,
                                     (size_t)KSEQ * KDIM, 0);
}

// round 16
// speedup vs baseline: 1.1693x; 1.0865x over previous
#include <cuda_runtime.h>
#include <cuda_fp16.h>
#include <cstdint>
#include <math.h>

// ---------------- problem constants ----------------
#define KBATCH 8
#define KSEQ   2048
#define KDIM   512
#define KROWS  (KBATCH*KSEQ)   // 16384

// ---------------- scratch (device globals; no allocations) ----------------
__device__ __half  g_in  [3][(size_t)KROWS * KDIM];  // Q,K,V inputs fp16
__device__ __half  g_w   [3][(size_t)KDIM * KDIM];   // W^T fp16 [e][d] = [N,K]
__device__ __half  g_qkv [3][(size_t)KROWS * KDIM];  // q_s, k_s, v_s fp16
__device__ __half  g_vt  [(size_t)KBATCH * KDIM * KSEQ]; // v_s^T fp16 [B][D][S]
__device__ __half  g_e   [(size_t)KBATCH * KSEQ * KSEQ]; // exp(scores) fp16
__device__ float   g_rs  [KROWS];                        // row sums of exp

// ---------------- helpers ----------------
__device__ __forceinline__ uint32_t smem_u32(const void* p) {
    uint32_t a;
    asm("{ .reg .u64 t; cvta.to.shared.u64 t, %1; cvt.u32.u64 %0, t; }" : "=r"(a) : "l"(p));
    return a;
}
__device__ __forceinline__ uint32_t pack2h(__half a, __half b) {
    return (uint32_t)__half_as_ushort(a) | ((uint32_t)__half_as_ushort(b) << 16);
}
__device__ __forceinline__ void ldmx4(uint32_t& r0, uint32_t& r1, uint32_t& r2, uint32_t& r3,
                                      uint32_t addr) {
    asm volatile("ldmatrix.sync.aligned.m8n8.x4.shared.b16 {%0,%1,%2,%3}, [%4];"
                 : "=r"(r0), "=r"(r1), "=r"(r2), "=r"(r3) : "r"(addr));
}
__device__ __forceinline__ void mma_f16(float* c, const uint32_t* a, uint32_t b0, uint32_t b1) {
    asm volatile("mma.sync.aligned.m16n8k16.row.col.f32.f16.f16.f32 "
                 "{%0,%1,%2,%3}, {%4,%5,%6,%7}, {%8,%9}, {%0,%1,%2,%3};"
                 : "+f"(c[0]), "+f"(c[1]), "+f"(c[2]), "+f"(c[3])
                 : "r"(a[0]), "r"(a[1]), "r"(a[2]), "r"(a[3]), "r"(b0), "r"(b1));
}
#define CP16(dst, src) \
    asm volatile("cp.async.cg.shared.global [%0], [%1], 16;" :: "r"(dst), "l"(src))
#define CP_COMMIT() asm volatile("cp.async.commit_group;" ::: "memory")

__device__ __forceinline__ float ssc() { return 0.044194173824159216f; } // 1/sqrt(512)

// ---------------- HMMA GEMM: 128 threads, CTA 128x128, warp tile 64x64 ----------------
// 2 CTAs per SM. Single-term fp16 (AhBh).
// EPI 2: /rowsum -> f32 (AV)    EPI 4: +bias(by z) -> fp16
// EPI 5: exp(acc*scale + mask) -> fp16, + rowsum atomics
#define TILE_M 128
#define TILE_N 128
#define TILE_K 32
#define GT 128
#define NST 4
#define PSTR 40                     // padded smem row stride (halves) -> 80 B/row
#define T_B (128 * PSTR * 2)        // 10240 bytes per 128x32 fp16 tile
#define STB (2 * T_B)               // stage: Ah + Bh
#define SMEM_T (NST * STB)          // 81920

template<int EPI>
__global__ __launch_bounds__(GT, 2)
void gemm_hmma(const __half* __restrict__ Ah,
               const __half* __restrict__ Bh,
               const float* __restrict__ aux,   // EPI5: mask. EPI2: unused.
               const float* __restrict__ aux2,  // EPI4: bias k. EPI5/2: rowsum base.
               const float* __restrict__ aux3,  // EPI4: bias v.
               float* __restrict__ C,
               __half* __restrict__ Ch,
               int N, int K,
               size_t sA, size_t sB, size_t sC, size_t sAux)
{
    extern __shared__ char sm[];
    const uint32_t sb = smem_u32(sm);

    Ah  += sA   * (size_t)blockIdx.z;
    Bh  += sB   * (size_t)blockIdx.z;
    C   += sC   * (size_t)blockIdx.z;
    Ch  += sC   * (size_t)blockIdx.z;
    aux += sAux * (size_t)blockIdx.z;
    const float* bias = aux;
    if (EPI == 4) bias = (blockIdx.z == 0) ? aux : (blockIdx.z == 1) ? aux2 : aux3;
    float* rsum = nullptr;
    if (EPI == 5 || EPI == 2)
        rsum = const_cast<float*>(aux2) + (size_t)blockIdx.z * KSEQ;

    const int t    = threadIdx.x;
    const int lane = t & 31;
    const int w    = t >> 5;        // 0..3
    const int wm   = w & 1;         // warp row (2) -> M offset 64*wm
    const int wn   = w >> 1;        // warp col (2) -> N offset 64*wn
    const int bm   = blockIdx.y * TILE_M;
    const int bn   = blockIdx.x * TILE_N;

    const int cr = t >> 2;          // 0..31
    const int cc = t & 3;           // 16B chunk within 64B row

    const int a_r  = wm * 64 + (lane & 15);
    const int a_c8 = (lane >> 4) * 8;
    const int b_r  = wn * 64 + (lane & 7) + ((lane >> 4) & 1) * 8;
    const int b_c8 = ((lane >> 3) & 1) * 8;

    float acc[4][8][4];
    #pragma unroll
    for (int i = 0; i < 4; ++i)
        #pragma unroll
        for (int j = 0; j < 8; ++j)
            #pragma unroll
            for (int e = 0; e < 4; ++e) acc[i][j][e] = 0.0f;

    const int nch = K / TILE_K;

    auto issue = [&](int j, int s) {
        const size_t kco = (size_t)j * TILE_K + cc * 8;
        const uint32_t base = sb + (uint32_t)(s * STB);
        #pragma unroll
        for (int p = 0; p < 4; ++p) {
            const int row = cr + p * 32;
            const uint32_t doff = (uint32_t)(row * (PSTR * 2) + cc * 16);
            CP16(base + doff,       Ah + (size_t)(bm + row) * K + kco);
            CP16(base + T_B + doff, Bh + (size_t)(bn + row) * K + kco);
        }
    };

    // prologue
    #pragma unroll
    for (int j = 0; j < NST - 1; ++j) {
        if (j < nch) issue(j, j);
        CP_COMMIT();
    }

    for (int i = 0; i < nch; ++i) {
        asm volatile("cp.async.wait_group %0;" :: "n"(NST - 2) : "memory");
        __syncthreads();

        const int jn = i + NST - 1;
        if (jn < nch) issue(jn, jn % NST);
        CP_COMMIT();

        const int s = i % NST;
        const uint32_t sAH = sb + (uint32_t)(s * STB);
        const uint32_t sBH = sAH + T_B;

        #pragma unroll
        for (int h = 0; h < 2; ++h) {
            const uint32_t bcol = (uint32_t)((h * 16 + b_c8) * 2);
            uint32_t bh[4][4];
            #pragma unroll
            for (int np = 0; np < 4; ++np) {
                const uint32_t boff = (uint32_t)((b_r + np * 16) * (PSTR * 2)) + bcol;
                ldmx4(bh[np][0], bh[np][1], bh[np][2], bh[np][3], sBH + boff);
            }
            const uint32_t acol = (uint32_t)((h * 16 + a_c8) * 2);
            #pragma unroll
            for (int mp = 0; mp < 2; ++mp) {
                uint32_t ahr[2][4];
                #pragma unroll
                for (int m2 = 0; m2 < 2; ++m2) {
                    const uint32_t aoff =
                        (uint32_t)((a_r + (mp * 2 + m2) * 16) * (PSTR * 2)) + acol;
                    ldmx4(ahr[m2][0], ahr[m2][1], ahr[m2][2], ahr[m2][3], sAH + aoff);
                }
                #pragma unroll
                for (int np = 0; np < 4; ++np)
                    #pragma unroll
                    for (int m2 = 0; m2 < 2; ++m2) {
                        mma_f16(acc[mp*2+m2][2*np],   ahr[m2], bh[np][0], bh[np][1]);
                        mma_f16(acc[mp*2+m2][2*np+1], ahr[m2], bh[np][2], bh[np][3]);
                    }
            }
        }
    }

    // ---------------- epilogue ----------------
    const int er = (lane >> 2);
    const int ec = (lane & 3) * 2;

    float inv[4][2];   // EPI2: per-(mt,half) reciprocal of rowsum
    if (EPI == 2) {
        #pragma unroll
        for (int mt = 0; mt < 4; ++mt)
            #pragma unroll
            for (int half = 0; half < 2; ++half) {
                const int row = wm * 64 + mt * 16 + er + half * 8;  // within batch tile row bm+
                inv[mt][half] = 1.0f / rsum[bm + row];
            }
    }

    float rs[4][2];
    if (EPI == 5) {
        #pragma unroll
        for (int mt = 0; mt < 4; ++mt) { rs[mt][0] = 0.0f; rs[mt][1] = 0.0f; }
    }

    #pragma unroll
    for (int mt = 0; mt < 4; ++mt) {
        #pragma unroll
        for (int nt = 0; nt < 8; ++nt) {
            const int col = bn + wn * 64 + nt * 8 + ec;
            #pragma unroll
            for (int half = 0; half < 2; ++half) {
                const int row = bm + wm * 64 + mt * 16 + er + half * 8;
                float x0 = acc[mt][nt][2*half + 0];
                float x1 = acc[mt][nt][2*half + 1];
                if (EPI == 4) {
                    x0 += bias[col];
                    x1 += bias[col + 1];
                }
                const size_t o = (size_t)row * N + col;
                if (EPI == 5) {
                    const float2 m2 = *reinterpret_cast<const float2*>(&aux[o]);
                    float e0 = __expf(fmaf(x0, ssc(), m2.x));
                    float e1 = __expf(fmaf(x1, ssc(), m2.y));
                    *reinterpret_cast<uint32_t*>(&Ch[o]) =
                        pack2h(__float2half(e0), __float2half(e1));
                    rs[mt][half] += e0 + e1;
                } else if (EPI == 4) {
                    *reinterpret_cast<uint32_t*>(&Ch[o]) =
                        pack2h(__float2half(x0), __float2half(x1));
                } else { // EPI 2
                    *reinterpret_cast<float2*>(&C[o]) =
                        make_float2(x0 * inv[mt][half], x1 * inv[mt][half]);
                }
            }
        }
    }

    if (EPI == 5) {
        // reduce across the 4 lanes of each quad (same row, different cols), then atomic
        #pragma unroll
        for (int mt = 0; mt < 4; ++mt)
            #pragma unroll
            for (int half = 0; half < 2; ++half) {
                float v = rs[mt][half];
                v += __shfl_xor_sync(0xffffffffu, v, 1);
                v += __shfl_xor_sync(0xffffffffu, v, 2);
                if ((lane & 3) == 0) {
                    const int row = bm + wm * 64 + mt * 16 + er + half * 8;
                    atomicAdd(&rsum[row], v);
                }
            }
    }
}

// ---------------- fused input convert: 3 tensors -> single fp16 ----------------
__global__ __launch_bounds__(256)
void convert_inputs(const float* __restrict__ q, const float* __restrict__ k,
                    const float* __restrict__ v, __half* __restrict__ dh)
{
    const size_t ISZ = (size_t)KROWS * KDIM;
    const float* src = (blockIdx.z == 0) ? q : (blockIdx.z == 1) ? k : v;
    __half* oh = dh + blockIdx.z * ISZ;
    const size_t i = ((size_t)blockIdx.x * 256 + threadIdx.x) * 4;
    float4 x = *reinterpret_cast<const float4*>(src + i);
    *reinterpret_cast<uint2*>(oh + i) =
        make_uint2(pack2h(__float2half(x.x), __float2half(x.y)),
                   pack2h(__float2half(x.z), __float2half(x.w)));
}

// ---------------- fused weight transpose -> single fp16 [e][d] ----------------
__global__ __launch_bounds__(256)
void wtrans(const float* __restrict__ wq, const float* __restrict__ wk,
            const float* __restrict__ wv, __half* __restrict__ dh)
{
    __shared__ float tile[32][33];
    const size_t WSZ = (size_t)KDIM * KDIM;
    const float* src = (blockIdx.z == 0) ? wq : (blockIdx.z == 1) ? wk : wv;
    __half* oh = dh + blockIdx.z * WSZ;
    const int bx = blockIdx.x * 32;
    const int by = blockIdx.y * 32;
    const int tx = threadIdx.x & 31;
    const int ty = threadIdx.x >> 5;
    #pragma unroll
    for (int i = 0; i < 32; i += 8)
        tile[ty + i][tx] = src[(size_t)(by + ty + i) * KDIM + bx + tx];
    __syncthreads();
    #pragma unroll
    for (int i = 0; i < 32; i += 8)
        oh[(size_t)(bx + ty + i) * KDIM + by + tx] = __float2half(tile[tx][ty + i]);
}

// ---------------- v transpose: fp16 [B][S][D] -> fp16 [B][D][S] ----------------
__global__ __launch_bounds__(256)
void vtrans(const __half* __restrict__ src, __half* __restrict__ dst)
{
    __shared__ __half tile[32][34];
    src += (size_t)KSEQ * KDIM * blockIdx.z;
    dst += (size_t)KDIM * KSEQ * blockIdx.z;
    const int bx = blockIdx.x * 32;   // D
    const int by = blockIdx.y * 32;   // S
    const int tx = threadIdx.x & 31;
    const int ty = threadIdx.x >> 5;
    #pragma unroll
    for (int i = 0; i < 32; i += 8)
        tile[ty + i][tx] = src[(size_t)(by + ty + i) * KDIM + bx + tx];
    __syncthreads();
    #pragma unroll
    for (int i = 0; i < 32; i += 8)
        dst[(size_t)(bx + ty + i) * KSEQ + by + tx] = tile[tx][ty + i];
}

// ---------------- launch ----------------
extern "C" void kernel_launch(void* const* d_in, const int* in_sizes, int n_in,
                              void* d_out, int out_size)
{
    (void)in_sizes; (void)n_in; (void)out_size;
    const float* Qin  = (const float*)d_in[0];
    const float* Kin  = (const float*)d_in[1];
    const float* Vin  = (const float*)d_in[2];
    const float* mask = (const float*)d_in[3];
    const float* Wq   = (const float*)d_in[4];
    const float* bq   = (const float*)d_in[5];
    const float* Wk   = (const float*)d_in[6];
    const float* bk   = (const float*)d_in[7];
    const float* Wv   = (const float*)d_in[8];
    const float* bv   = (const float*)d_in[9];
    float* out = (float*)d_out;

    float *rs;
    __half *in16, *w16, *qkv, *vt, *eh;
    cudaGetSymbolAddress((void**)&in16, g_in);
    cudaGetSymbolAddress((void**)&w16,  g_w);
    cudaGetSymbolAddress((void**)&qkv,  g_qkv);
    cudaGetSymbolAddress((void**)&vt,   g_vt);
    cudaGetSymbolAddress((void**)&eh,   g_e);
    cudaGetSymbolAddress((void**)&rs,   g_rs);

    cudaFuncSetAttribute(gemm_hmma<4>, cudaFuncAttributeMaxDynamicSharedMemorySize, SMEM_T);
    cudaFuncSetAttribute(gemm_hmma<5>, cudaFuncAttributeMaxDynamicSharedMemorySize, SMEM_T);
    cudaFuncSetAttribute(gemm_hmma<2>, cudaFuncAttributeMaxDynamicSharedMemorySize, SMEM_T);

    const size_t ISZ = (size_t)KROWS * KDIM;
    const size_t WSZ = (size_t)KDIM * KDIM;
    dim3 tb(256);

    // 0) zero row sums (graph-capturable, no allocation)
    cudaMemsetAsync(rs, 0, KROWS * sizeof(float));

    // 1-2) preprocessing: inputs + weights -> single fp16
    convert_inputs<<<dim3((int)(ISZ / 4 / 256), 1, 3), tb>>>(Qin, Kin, Vin, in16);
    wtrans<<<dim3(16, 16, 3), tb>>>(Wq, Wk, Wv, w16);

    // 3) fused Q/K/V projections (one launch; z selects operands & bias)
    dim3 gp(KDIM / TILE_N, KROWS / TILE_M, 3);
    gemm_hmma<4><<<gp, GT, SMEM_T>>>(in16, w16, bq, bk, bv,
                                     nullptr, qkv, KDIM, KDIM,
                                     ISZ, WSZ, ISZ, 0);

    // 4) exp(scores) = exp(q k^T * scale + mask) -> fp16, + row sums
    dim3 gs(KSEQ / TILE_N, KSEQ / TILE_M, KBATCH);
    gemm_hmma<5><<<gs, GT, SMEM_T>>>(qkv + 0*ISZ, qkv + 1*ISZ, mask, rs, nullptr,
                                     nullptr, eh, KSEQ, KDIM,
                                     (size_t)KSEQ * KDIM, (size_t)KSEQ * KDIM,
                                     (size_t)KSEQ * KSEQ, (size_t)KSEQ * KSEQ);

    // 5) v_s -> v_s^T (fp16 -> fp16)
    vtrans<<<dim3(KDIM / 32, KSEQ / 32, KBATCH), tb>>>(qkv + 2*ISZ, vt);

    // 6) out = (exp @ v_s) / rowsum   (per batch 2048x512, K=2048)
    dim3 ga(KDIM / TILE_N, KSEQ / TILE_M, KBATCH);
    gemm_hmma<2><<<ga, GT, SMEM_T>>>(eh, vt, nullptr, rs, nullptr,
                                     out, nullptr, KDIM, KSEQ,
                                     (size_t)KSEQ * KSEQ, (size_t)KDIM * KSEQ,
                                     (size_t)KSEQ * KDIM, 0);
}